// round 1
// baseline (speedup 1.0000x reference)
#include <cuda_runtime.h>
#include <cuda_bf16.h>
#include <math.h>

// Problem constants
#define BATCH 16384
#define NJ 16
#define HID 128
#define MROWS (BATCH*NJ)        // 262144
#define KC 16                   // K chunk (per W matrix) for mid GEMM

// Skeleton adjacency (incl. self) as row bitmasks, from EDGES in the reference.
__constant__ unsigned int c_maskrow[16] = {
    0x0093u, 0x0007u, 0x000Eu, 0x000Cu,
    0x0031u, 0x0070u, 0x0060u, 0x0181u,
    0x4B80u, 0x0700u, 0x0600u, 0x1900u,
    0x3800u, 0x3000u, 0xC100u, 0xC000u
};

// Scratch activations (allowed: __device__ globals, no runtime alloc)
__device__ float g_h[MROWS * HID];   // 128 MB
__device__ float g_t[MROWS * HID];   // 128 MB

// Precomputed per-layer graph/BN data. Layers: 0=in, 1..8=mid, 9=out.
__device__ float g_d[10][16];          // diagonal of softmax(A)
__device__ float g_Aoff[10][16][16];   // off-diagonal A (diag zeroed)
__device__ float g_scale[9][HID];      // BN scale (layers 0..8)
__device__ float g_shift[9][HID];      // BN shift with conv bias folded in

// ---------- packed f32x2 helpers ----------
__device__ __forceinline__ unsigned long long pack2(float x, float y) {
    unsigned long long r;
    asm("mov.b64 %0, {%1,%2};" : "=l"(r) : "f"(x), "f"(y));
    return r;
}
__device__ __forceinline__ void unpack2(unsigned long long v, float &x, float &y) {
    asm("mov.b64 {%0,%1}, %2;" : "=f"(x), "=f"(y) : "l"(v));
}
__device__ __forceinline__ unsigned long long ffma2(unsigned long long a,
                                                    unsigned long long b,
                                                    unsigned long long c) {
    unsigned long long d;
    asm("fma.rn.f32x2 %0, %1, %2, %3;" : "=l"(d) : "l"(a), "l"(b), "l"(c));
    return d;
}

// ---------- prep: softmax A matrices + folded BN params ----------
__global__ void prep_kernel(const float* __restrict__ e_in,
                            const float* __restrict__ bn_in,
                            const float* __restrict__ b_in,
                            const float* __restrict__ e_mid,
                            const float* __restrict__ bn_mid,
                            const float* __restrict__ b_mid,
                            const float* __restrict__ e_out) {
    int t = threadIdx.x;
    // A matrices: 10 layers x 16 rows
    if (t < 160) {
        int l = t >> 4, i = t & 15;
        const float* e = (l == 0) ? e_in : ((l <= 8) ? (e_mid + (l - 1) * 256) : e_out);
        unsigned int m = c_maskrow[i];
        float mx = -3.4e38f;
        for (int j = 0; j < 16; j++)
            if ((m >> j) & 1u) mx = fmaxf(mx, e[i * 16 + j]);
        float a[16];
        float s = 0.f;
        for (int j = 0; j < 16; j++) {
            float v = ((m >> j) & 1u) ? expf(e[i * 16 + j] - mx) : 0.f;
            a[j] = v; s += v;
        }
        float inv = 1.f / s;
        g_d[l][i] = a[i] * inv;
        for (int j = 0; j < 16; j++)
            g_Aoff[l][i][j] = (j == i) ? 0.f : a[j] * inv;
    }
    // BN params: layers 0..8, 128 feats each (fold conv bias into shift)
    for (int idx = t; idx < 9 * HID; idx += blockDim.x) {
        int lb = idx >> 7, f = idx & 127;
        float gamma, beta, mean, var, bias;
        if (lb == 0) {
            gamma = bn_in[f]; beta = bn_in[128 + f];
            mean = bn_in[256 + f]; var = bn_in[384 + f];
            bias = b_in[f];
        } else {
            const float* base = bn_mid + (lb - 1) * 512;
            gamma = base[f]; beta = base[128 + f];
            mean = base[256 + f]; var = base[384 + f];
            bias = b_mid[(lb - 1) * 128 + f];
        }
        float sc = gamma * rsqrtf(var + 1e-5f);
        g_scale[lb][f] = sc;
        g_shift[lb][f] = beta - mean * sc + bias * sc;
    }
}

// ---------- input layer: (B,16,2) -> (B,16,128), bn_relu ----------
__global__ void __launch_bounds__(128) in_kernel(const float* __restrict__ x,
                                                 const float* __restrict__ Win) {
    __shared__ float xs[16][2];
    __shared__ float sd[16];
    __shared__ float sAoff[16][16];
    int b = blockIdx.x, t = threadIdx.x;
    if (t < 32) ((float*)xs)[t] = x[b * 32 + t];
    if (t < 16) sd[t] = g_d[0][t];
    for (int e = t; e < 256; e += 128)
        sAoff[e >> 4][e & 15] = g_Aoff[0][e >> 4][e & 15];
    __syncthreads();
    int f = t;
    float w00 = Win[f], w01 = Win[128 + f], w10 = Win[256 + f], w11 = Win[384 + f];
    float q[16];
#pragma unroll
    for (int j = 0; j < 16; j++) q[j] = xs[j][0] * w10 + xs[j][1] * w11;
    float sc = g_scale[0][f], sh = g_shift[0][f];
#pragma unroll
    for (int i = 0; i < 16; i++) {
        float o = sd[i] * (xs[i][0] * w00 + xs[i][1] * w01);
#pragma unroll
        for (int j = 0; j < 16; j++) o += sAoff[i][j] * q[j];
        o = fmaxf(o * sc + sh, 0.f);
        g_h[(b * 16 + i) * HID + f] = o;
    }
}

// ---------- mid layer: premixed GEMM (M=128/CTA, N=128, K=256) ----------
// src=0: read g_h, write g_t; src=1: read g_t, write g_h (+residual from g_h)
__global__ void __launch_bounds__(256) mid_kernel(const float* __restrict__ Wp,
                                                  int layer, int src, int residAdd) {
    __shared__ __align__(16) float Xs[128][KC + 1];
    __shared__ __align__(16) float As[2 * KC][128];
    __shared__ __align__(16) float Bs[2 * KC][128];
    __shared__ float sd[16];
    __shared__ float sAoff[16][16];

    const float* X = src ? g_t : g_h;
    float* Y       = src ? g_h : g_t;
    const float* R = residAdd ? g_h : nullptr;

    int t = threadIdx.x;
    int m0 = blockIdx.x * 128;
    if (t < 16) sd[t] = g_d[layer][t];
    sAoff[t >> 4][t & 15] = g_Aoff[layer][t >> 4][t & 15];

    unsigned long long acc[8][4];
#pragma unroll
    for (int m = 0; m < 8; m++)
#pragma unroll
        for (int p = 0; p < 4; p++) acc[m][p] = pack2(0.f, 0.f);

    int tx = t & 15, ty = t >> 4;
    int r0 = ty * 8, c0 = tx * 8;

    for (int kc = 0; kc < HID / KC; ++kc) {
        int k0 = kc * KC;
        __syncthreads();
        // load X chunk (128 rows x KC)
        for (int idx = t; idx < 512; idx += 256) {
            int r = idx >> 2, q = idx & 3;
            float4 v = *(const float4*)&X[(m0 + r) * HID + k0 + q * 4];
            Xs[r][q * 4 + 0] = v.x; Xs[r][q * 4 + 1] = v.y;
            Xs[r][q * 4 + 2] = v.z; Xs[r][q * 4 + 3] = v.w;
        }
        // load W chunk: rows 0..KC-1 = W0[k0+kk], rows KC.. = W1[k0+kk-KC]
        for (int idx = t; idx < 1024; idx += 256) {
            int kk = idx >> 5, q = idx & 31;
            const float* srcp = (kk < KC) ? (Wp + (k0 + kk) * HID)
                                          : (Wp + HID * HID + (k0 + kk - KC) * HID);
            *(float4*)&Bs[kk][q * 4] = *(const float4*)&srcp[q * 4];
        }
        __syncthreads();
        // premix: U = d_i * x ; V = Aoff @ x (within each 16-joint group)
        for (int idx = t; idx < 128 * KC; idx += 256) {
            int r = idx & 127, c = idx >> 7;
            int i = r & 15, rb = r & ~15;
            As[c][r] = sd[i] * Xs[r][c];
            float v = 0.f;
#pragma unroll
            for (int j = 0; j < 16; j++) v += sAoff[i][j] * Xs[rb + j][c];
            As[KC + c][r] = v;
        }
        __syncthreads();
        // GEMM over 2*KC
#pragma unroll 8
        for (int kk = 0; kk < 2 * KC; ++kk) {
            float4 a0 = *(const float4*)&As[kk][r0];
            float4 a1 = *(const float4*)&As[kk][r0 + 4];
            float4 b0 = *(const float4*)&Bs[kk][c0];
            float4 b1 = *(const float4*)&Bs[kk][c0 + 4];
            unsigned long long bp0 = pack2(b0.x, b0.y);
            unsigned long long bp1 = pack2(b0.z, b0.w);
            unsigned long long bp2 = pack2(b1.x, b1.y);
            unsigned long long bp3 = pack2(b1.z, b1.w);
            float am[8] = {a0.x, a0.y, a0.z, a0.w, a1.x, a1.y, a1.z, a1.w};
#pragma unroll
            for (int m = 0; m < 8; m++) {
                unsigned long long ap = pack2(am[m], am[m]);
                acc[m][0] = ffma2(ap, bp0, acc[m][0]);
                acc[m][1] = ffma2(ap, bp1, acc[m][1]);
                acc[m][2] = ffma2(ap, bp2, acc[m][2]);
                acc[m][3] = ffma2(ap, bp3, acc[m][3]);
            }
        }
    }
    // epilogue: bn_relu (+ residual)
    float sc[8], sh[8];
#pragma unroll
    for (int n = 0; n < 8; n++) {
        sc[n] = g_scale[layer][c0 + n];
        sh[n] = g_shift[layer][c0 + n];
    }
#pragma unroll
    for (int m = 0; m < 8; m++) {
        int row = m0 + r0 + m;
        int base = row * HID;
#pragma unroll
        for (int p = 0; p < 4; p++) {
            float y0, y1;
            unpack2(acc[m][p], y0, y1);
            int c = c0 + p * 2;
            y0 = fmaxf(y0 * sc[p * 2] + sh[p * 2], 0.f);
            y1 = fmaxf(y1 * sc[p * 2 + 1] + sh[p * 2 + 1], 0.f);
            if (R) { y0 += R[base + c]; y1 += R[base + c + 1]; }
            float2 v; v.x = y0; v.y = y1;
            *(float2*)&Y[base + c] = v;
        }
    }
}

// ---------- output layer + MDN head ----------
__global__ void __launch_bounds__(128) out_kernel(const float* __restrict__ Wout,
                                                  const float* __restrict__ bout,
                                                  float* __restrict__ out) {
    __shared__ float hb[16][132];
    __shared__ float Wsf[256 * 26];   // [sel*128+k][c] stride 26
    __shared__ float ps[50][17];      // [sel*25+c][i]
    __shared__ float sd[16];
    __shared__ float sAoff[16][16];
    int b = blockIdx.x, t = threadIdx.x;
    if (t < 16) sd[t] = g_d[9][t];
    for (int e = t; e < 256; e += 128)
        sAoff[e >> 4][e & 15] = g_Aoff[9][e >> 4][e & 15];
    for (int i = 0; i < 16; i++)
        hb[i][t] = g_h[(b * 16 + i) * HID + t];
    for (int idx = t; idx < 6400; idx += 128) {
        int s = idx / 3200;
        int r = idx - s * 3200;
        int k = r / 25;
        int c = r - k * 25;
        Wsf[(s * 128 + k) * 26 + c] = Wout[idx];
    }
    __syncthreads();

    // partial dots: p[sel][c][i] = hb[i] . W_sel[:, c]
    int i = t >> 3, g = t & 7;
    float acc[7];
    int off[7], uu[7];
    int nq = 0;
    for (int u = g; u < 50; u += 8) {
        int sel = u / 25, c = u - sel * 25;
        off[nq] = sel * (128 * 26) + c;
        uu[nq] = u;
        acc[nq] = 0.f;
        nq++;
    }
    for (int k = 0; k < HID; k++) {
        float h = hb[i][k];
        int kb = k * 26;
#pragma unroll
        for (int q = 0; q < 7; q++)
            if (q < nq) acc[q] += h * Wsf[off[q] + kb];
    }
#pragma unroll
    for (int q = 0; q < 7; q++)
        if (q < nq) ps[uu[q]][i] = acc[q];
    __syncthreads();

    // mix + MDN head
    for (int e = t; e < 400; e += 128) {
        int i2 = e / 25, c = e - i2 * 25;
        float o = sd[i2] * ps[c][i2] + bout[c];
#pragma unroll
        for (int j = 0; j < 16; j++) o += sAoff[i2][j] * ps[25 + c][j];
        int row = b * 16 + i2;
        if (c < 15) {
            out[row * 15 + c] = tanhf(o);
        } else if (c < 20) {
            float s = (o > 0.f) ? (o + 1.f) : expf(o);
            out[BATCH * NJ * 15 + row * 5 + (c - 15)] = fmaxf(s, 1e-10f);
        } else {
            out[BATCH * NJ * 20 + row * 5 + (c - 20)] = o;
        }
    }
}

extern "C" void kernel_launch(void* const* d_in, const int* in_sizes, int n_in,
                              void* d_out, int out_size) {
    const float* x      = (const float*)d_in[0];
    const float* W_in   = (const float*)d_in[1];
    const float* e_in   = (const float*)d_in[2];
    const float* b_in   = (const float*)d_in[3];
    const float* bn_in  = (const float*)d_in[4];
    const float* W_mid  = (const float*)d_in[5];
    const float* e_mid  = (const float*)d_in[6];
    const float* b_mid  = (const float*)d_in[7];
    const float* bn_mid = (const float*)d_in[8];
    const float* W_out  = (const float*)d_in[9];
    const float* e_out  = (const float*)d_in[10];
    const float* b_out  = (const float*)d_in[11];
    float* out = (float*)d_out;

    prep_kernel<<<1, 256>>>(e_in, bn_in, b_in, e_mid, bn_mid, b_mid, e_out);
    in_kernel<<<BATCH, 128>>>(x, W_in);

    const int nblk = MROWS / 128;  // 2048
    for (int p = 0; p < 4; p++) {
        // first of pair: g_h -> g_t
        mid_kernel<<<nblk, 256>>>(W_mid + (2 * p) * 2 * HID * HID, 1 + 2 * p, 0, 0);
        // second of pair: g_t -> g_h, + residual (old g_h)
        mid_kernel<<<nblk, 256>>>(W_mid + (2 * p + 1) * 2 * HID * HID, 2 + 2 * p, 1, 1);
    }
    out_kernel<<<BATCH, 128>>>(W_out, b_out, out);
}

// round 2
// speedup vs baseline: 1.0001x; 1.0001x over previous
#include <cuda_runtime.h>
#include <cuda_bf16.h>
#include <math.h>

// Problem constants
#define BATCH 16384
#define NJ 16
#define HID 128
#define MROWS (BATCH*NJ)        // 262144
#define KC 16                   // K chunk (per W matrix) for mid GEMM

// Skeleton adjacency (incl. self) as row bitmasks, from EDGES in the reference.
__constant__ unsigned int c_maskrow[16] = {
    0x0093u, 0x0007u, 0x000Eu, 0x000Cu,
    0x0031u, 0x0070u, 0x0060u, 0x0181u,
    0x4B80u, 0x0700u, 0x0600u, 0x1900u,
    0x3800u, 0x3000u, 0xC100u, 0xC000u
};

// Scratch activations (allowed: __device__ globals, no runtime alloc)
__device__ float g_h[MROWS * HID];   // 128 MB
__device__ float g_t[MROWS * HID];   // 128 MB

// Precomputed per-layer graph/BN data. Layers: 0=in, 1..8=mid, 9=out.
__device__ float g_d[10][16];          // diagonal of softmax(A)
__device__ float g_Aoff[10][16][16];   // off-diagonal A (diag zeroed)
__device__ float g_scale[9][HID];      // BN scale (layers 0..8)
__device__ float g_shift[9][HID];      // BN shift with conv bias folded in

// ---------- packed f32x2 helpers ----------
__device__ __forceinline__ unsigned long long pack2(float x, float y) {
    unsigned long long r;
    asm("mov.b64 %0, {%1,%2};" : "=l"(r) : "f"(x), "f"(y));
    return r;
}
__device__ __forceinline__ void unpack2(unsigned long long v, float &x, float &y) {
    asm("mov.b64 {%0,%1}, %2;" : "=f"(x), "=f"(y) : "l"(v));
}
__device__ __forceinline__ unsigned long long ffma2(unsigned long long a,
                                                    unsigned long long b,
                                                    unsigned long long c) {
    unsigned long long d;
    asm("fma.rn.f32x2 %0, %1, %2, %3;" : "=l"(d) : "l"(a), "l"(b), "l"(c));
    return d;
}

// ---------- prep: softmax A matrices + folded BN params ----------
__global__ void prep_kernel(const float* __restrict__ e_in,
                            const float* __restrict__ bn_in,
                            const float* __restrict__ b_in,
                            const float* __restrict__ e_mid,
                            const float* __restrict__ bn_mid,
                            const float* __restrict__ b_mid,
                            const float* __restrict__ e_out) {
    int t = threadIdx.x;
    // A matrices: 10 layers x 16 rows
    if (t < 160) {
        int l = t >> 4, i = t & 15;
        const float* e = (l == 0) ? e_in : ((l <= 8) ? (e_mid + (l - 1) * 256) : e_out);
        unsigned int m = c_maskrow[i];
        float mx = -3.4e38f;
        for (int j = 0; j < 16; j++)
            if ((m >> j) & 1u) mx = fmaxf(mx, e[i * 16 + j]);
        float a[16];
        float s = 0.f;
        for (int j = 0; j < 16; j++) {
            float v = ((m >> j) & 1u) ? expf(e[i * 16 + j] - mx) : 0.f;
            a[j] = v; s += v;
        }
        float inv = 1.f / s;
        g_d[l][i] = a[i] * inv;
        for (int j = 0; j < 16; j++)
            g_Aoff[l][i][j] = (j == i) ? 0.f : a[j] * inv;
    }
    // BN params: layers 0..8, 128 feats each (fold conv bias into shift)
    for (int idx = t; idx < 9 * HID; idx += blockDim.x) {
        int lb = idx >> 7, f = idx & 127;
        float gamma, beta, mean, var, bias;
        if (lb == 0) {
            gamma = bn_in[f]; beta = bn_in[128 + f];
            mean = bn_in[256 + f]; var = bn_in[384 + f];
            bias = b_in[f];
        } else {
            const float* base = bn_mid + (lb - 1) * 512;
            gamma = base[f]; beta = base[128 + f];
            mean = base[256 + f]; var = base[384 + f];
            bias = b_mid[(lb - 1) * 128 + f];
        }
        float sc = gamma * rsqrtf(var + 1e-5f);
        g_scale[lb][f] = sc;
        g_shift[lb][f] = beta - mean * sc + bias * sc;
    }
}

// ---------- input layer: (B,16,2) -> (B,16,128), bn_relu ----------
__global__ void __launch_bounds__(128) in_kernel(const float* __restrict__ x,
                                                 const float* __restrict__ Win) {
    __shared__ float xs[16][2];
    __shared__ float sd[16];
    __shared__ float sAoff[16][16];
    int b = blockIdx.x, t = threadIdx.x;
    if (t < 32) ((float*)xs)[t] = x[b * 32 + t];
    if (t < 16) sd[t] = g_d[0][t];
    for (int e = t; e < 256; e += 128)
        sAoff[e >> 4][e & 15] = g_Aoff[0][e >> 4][e & 15];
    __syncthreads();
    int f = t;
    float w00 = Win[f], w01 = Win[128 + f], w10 = Win[256 + f], w11 = Win[384 + f];
    float q[16];
#pragma unroll
    for (int j = 0; j < 16; j++) q[j] = xs[j][0] * w10 + xs[j][1] * w11;
    float sc = g_scale[0][f], sh = g_shift[0][f];
#pragma unroll
    for (int i = 0; i < 16; i++) {
        float o = sd[i] * (xs[i][0] * w00 + xs[i][1] * w01);
#pragma unroll
        for (int j = 0; j < 16; j++) o += sAoff[i][j] * q[j];
        o = fmaxf(o * sc + sh, 0.f);
        g_h[(b * 16 + i) * HID + f] = o;
    }
}

// ---------- mid layer: premixed GEMM (M=128/CTA, N=128, K=256) ----------
// src=0: read g_h, write g_t; src=1: read g_t, write g_h (+residual from g_h)
__global__ void __launch_bounds__(256) mid_kernel(const float* __restrict__ Wp,
                                                  int layer, int src, int residAdd) {
    __shared__ __align__(16) float Xs[128][KC + 1];
    __shared__ __align__(16) float As[2 * KC][128];
    __shared__ __align__(16) float Bs[2 * KC][128];
    __shared__ float sd[16];
    __shared__ float sAoff[16][16];

    const float* X = src ? g_t : g_h;
    float* Y       = src ? g_h : g_t;
    const float* R = residAdd ? g_h : nullptr;

    int t = threadIdx.x;
    int m0 = blockIdx.x * 128;
    if (t < 16) sd[t] = g_d[layer][t];
    sAoff[t >> 4][t & 15] = g_Aoff[layer][t >> 4][t & 15];

    unsigned long long acc[8][4];
#pragma unroll
    for (int m = 0; m < 8; m++)
#pragma unroll
        for (int p = 0; p < 4; p++) acc[m][p] = pack2(0.f, 0.f);

    int tx = t & 15, ty = t >> 4;
    int r0 = ty * 8, c0 = tx * 8;

    for (int kc = 0; kc < HID / KC; ++kc) {
        int k0 = kc * KC;
        __syncthreads();
        // load X chunk (128 rows x KC)
        for (int idx = t; idx < 512; idx += 256) {
            int r = idx >> 2, q = idx & 3;
            float4 v = *(const float4*)&X[(m0 + r) * HID + k0 + q * 4];
            Xs[r][q * 4 + 0] = v.x; Xs[r][q * 4 + 1] = v.y;
            Xs[r][q * 4 + 2] = v.z; Xs[r][q * 4 + 3] = v.w;
        }
        // load W chunk: rows 0..KC-1 = W0[k0+kk], rows KC.. = W1[k0+kk-KC]
        for (int idx = t; idx < 1024; idx += 256) {
            int kk = idx >> 5, q = idx & 31;
            const float* srcp = (kk < KC) ? (Wp + (k0 + kk) * HID)
                                          : (Wp + HID * HID + (k0 + kk - KC) * HID);
            *(float4*)&Bs[kk][q * 4] = *(const float4*)&srcp[q * 4];
        }
        __syncthreads();
        // premix: U = d_i * x ; V = Aoff @ x (within each 16-joint group)
        for (int idx = t; idx < 128 * KC; idx += 256) {
            int r = idx & 127, c = idx >> 7;
            int i = r & 15, rb = r & ~15;
            As[c][r] = sd[i] * Xs[r][c];
            float v = 0.f;
#pragma unroll
            for (int j = 0; j < 16; j++) v += sAoff[i][j] * Xs[rb + j][c];
            As[KC + c][r] = v;
        }
        __syncthreads();
        // GEMM over 2*KC
#pragma unroll 8
        for (int kk = 0; kk < 2 * KC; ++kk) {
            float4 a0 = *(const float4*)&As[kk][r0];
            float4 a1 = *(const float4*)&As[kk][r0 + 4];
            float4 b0 = *(const float4*)&Bs[kk][c0];
            float4 b1 = *(const float4*)&Bs[kk][c0 + 4];
            unsigned long long bp0 = pack2(b0.x, b0.y);
            unsigned long long bp1 = pack2(b0.z, b0.w);
            unsigned long long bp2 = pack2(b1.x, b1.y);
            unsigned long long bp3 = pack2(b1.z, b1.w);
            float am[8] = {a0.x, a0.y, a0.z, a0.w, a1.x, a1.y, a1.z, a1.w};
#pragma unroll
            for (int m = 0; m < 8; m++) {
                unsigned long long ap = pack2(am[m], am[m]);
                acc[m][0] = ffma2(ap, bp0, acc[m][0]);
                acc[m][1] = ffma2(ap, bp1, acc[m][1]);
                acc[m][2] = ffma2(ap, bp2, acc[m][2]);
                acc[m][3] = ffma2(ap, bp3, acc[m][3]);
            }
        }
    }
    // epilogue: bn_relu (+ residual)
    float sc[8], sh[8];
#pragma unroll
    for (int n = 0; n < 8; n++) {
        sc[n] = g_scale[layer][c0 + n];
        sh[n] = g_shift[layer][c0 + n];
    }
#pragma unroll
    for (int m = 0; m < 8; m++) {
        int row = m0 + r0 + m;
        int base = row * HID;
#pragma unroll
        for (int p = 0; p < 4; p++) {
            float y0, y1;
            unpack2(acc[m][p], y0, y1);
            int c = c0 + p * 2;
            y0 = fmaxf(y0 * sc[p * 2] + sh[p * 2], 0.f);
            y1 = fmaxf(y1 * sc[p * 2 + 1] + sh[p * 2 + 1], 0.f);
            if (R) { y0 += R[base + c]; y1 += R[base + c + 1]; }
            float2 v; v.x = y0; v.y = y1;
            *(float2*)&Y[base + c] = v;
        }
    }
}

// ---------- output layer + MDN head ----------
__global__ void __launch_bounds__(128) out_kernel(const float* __restrict__ Wout,
                                                  const float* __restrict__ bout,
                                                  float* __restrict__ out) {
    __shared__ float hb[16][132];
    __shared__ float Wsf[256 * 26];   // [sel*128+k][c] stride 26
    __shared__ float ps[50][17];      // [sel*25+c][i]
    __shared__ float sd[16];
    __shared__ float sAoff[16][16];
    int b = blockIdx.x, t = threadIdx.x;
    if (t < 16) sd[t] = g_d[9][t];
    for (int e = t; e < 256; e += 128)
        sAoff[e >> 4][e & 15] = g_Aoff[9][e >> 4][e & 15];
    for (int i = 0; i < 16; i++)
        hb[i][t] = g_h[(b * 16 + i) * HID + t];
    for (int idx = t; idx < 6400; idx += 128) {
        int s = idx / 3200;
        int r = idx - s * 3200;
        int k = r / 25;
        int c = r - k * 25;
        Wsf[(s * 128 + k) * 26 + c] = Wout[idx];
    }
    __syncthreads();

    // partial dots: p[sel][c][i] = hb[i] . W_sel[:, c]
    int i = t >> 3, g = t & 7;
    float acc[7];
    int off[7], uu[7];
    int nq = 0;
    for (int u = g; u < 50; u += 8) {
        int sel = u / 25, c = u - sel * 25;
        off[nq] = sel * (128 * 26) + c;
        uu[nq] = u;
        acc[nq] = 0.f;
        nq++;
    }
    for (int k = 0; k < HID; k++) {
        float h = hb[i][k];
        int kb = k * 26;
#pragma unroll
        for (int q = 0; q < 7; q++)
            if (q < nq) acc[q] += h * Wsf[off[q] + kb];
    }
#pragma unroll
    for (int q = 0; q < 7; q++)
        if (q < nq) ps[uu[q]][i] = acc[q];
    __syncthreads();

    // mix + MDN head
    for (int e = t; e < 400; e += 128) {
        int i2 = e / 25, c = e - i2 * 25;
        float o = sd[i2] * ps[c][i2] + bout[c];
#pragma unroll
        for (int j = 0; j < 16; j++) o += sAoff[i2][j] * ps[25 + c][j];
        int row = b * 16 + i2;
        if (c < 15) {
            out[row * 15 + c] = tanhf(o);
        } else if (c < 20) {
            float s = (o > 0.f) ? (o + 1.f) : expf(o);
            out[BATCH * NJ * 15 + row * 5 + (c - 15)] = fmaxf(s, 1e-10f);
        } else {
            out[BATCH * NJ * 20 + row * 5 + (c - 20)] = o;
        }
    }
}

extern "C" void kernel_launch(void* const* d_in, const int* in_sizes, int n_in,
                              void* d_out, int out_size) {
    const float* x      = (const float*)d_in[0];
    const float* W_in   = (const float*)d_in[1];
    const float* e_in   = (const float*)d_in[2];
    const float* b_in   = (const float*)d_in[3];
    const float* bn_in  = (const float*)d_in[4];
    const float* W_mid  = (const float*)d_in[5];
    const float* e_mid  = (const float*)d_in[6];
    const float* b_mid  = (const float*)d_in[7];
    const float* bn_mid = (const float*)d_in[8];
    const float* W_out  = (const float*)d_in[9];
    const float* e_out  = (const float*)d_in[10];
    const float* b_out  = (const float*)d_in[11];
    float* out = (float*)d_out;

    prep_kernel<<<1, 256>>>(e_in, bn_in, b_in, e_mid, bn_mid, b_mid, e_out);
    in_kernel<<<BATCH, 128>>>(x, W_in);

    const int nblk = MROWS / 128;  // 2048
    for (int p = 0; p < 4; p++) {
        // first of pair: g_h -> g_t
        mid_kernel<<<nblk, 256>>>(W_mid + (2 * p) * 2 * HID * HID, 1 + 2 * p, 0, 0);
        // second of pair: g_t -> g_h, + residual (old g_h)
        mid_kernel<<<nblk, 256>>>(W_mid + (2 * p + 1) * 2 * HID * HID, 2 + 2 * p, 1, 1);
    }
    out_kernel<<<BATCH, 128>>>(W_out, b_out, out);
}

// round 4
// speedup vs baseline: 1.5284x; 1.5283x over previous
#include <cuda_runtime.h>
#include <cuda_fp16.h>
#include <math.h>
#include <stdint.h>

#define BATCH 16384
#define NJ 16
#define HID 128
#define MROWS (BATCH*NJ)

__constant__ unsigned int c_maskrow[16] = {
    0x0093u, 0x0007u, 0x000Eu, 0x000Cu,
    0x0031u, 0x0070u, 0x0060u, 0x0181u,
    0x4B80u, 0x0700u, 0x0600u, 0x1900u,
    0x3800u, 0x3000u, 0xC100u, 0xC000u
};

__device__ float g_h[MROWS * HID];
__device__ float g_t[MROWS * HID];
__device__ float g_d[10][16];
__device__ float g_Aoff[10][16][16];
__device__ float g_scale[9][HID];
__device__ float g_shift[9][HID];
// weight fragments: [l][sc=8][pair=2][plane=2][n8=16][lane=32][4 halves]
__device__ __half g_Bfrag[8 * 8 * 2 * 2 * 16 * 32 * 4];

__device__ __forceinline__ unsigned long long pack2(float x, float y) {
    unsigned long long r;
    asm("mov.b64 %0, {%1,%2};" : "=l"(r) : "f"(x), "f"(y));
    return r;
}
__device__ __forceinline__ void unpack2(unsigned long long v, float &x, float &y) {
    asm("mov.b64 {%0,%1}, %2;" : "=f"(x), "=f"(y) : "l"(v));
}
__device__ __forceinline__ unsigned long long ffma2(unsigned long long a,
                                                    unsigned long long b,
                                                    unsigned long long c) {
    unsigned long long d;
    asm("fma.rn.f32x2 %0, %1, %2, %3;" : "=l"(d) : "l"(a), "l"(b), "l"(c));
    return d;
}
__device__ __forceinline__ void mma16816(float* c, const uint32_t* a,
                                         uint32_t b0, uint32_t b1) {
    asm volatile(
        "mma.sync.aligned.m16n8k16.row.col.f32.f16.f16.f32 "
        "{%0,%1,%2,%3},{%4,%5,%6,%7},{%8,%9},{%0,%1,%2,%3};"
        : "+f"(c[0]), "+f"(c[1]), "+f"(c[2]), "+f"(c[3])
        : "r"(a[0]), "r"(a[1]), "r"(a[2]), "r"(a[3]), "r"(b0), "r"(b1));
}
__device__ __forceinline__ void ldm4(uint32_t* d, uint32_t sa) {
    asm volatile("ldmatrix.sync.aligned.m8n8.x4.shared.b16 {%0,%1,%2,%3}, [%4];"
                 : "=r"(d[0]), "=r"(d[1]), "=r"(d[2]), "=r"(d[3]) : "r"(sa));
}
__device__ __forceinline__ void lds64(uint32_t& a, uint32_t& b, uint32_t sa) {
    asm volatile("ld.shared.v2.b32 {%0,%1}, [%2];" : "=r"(a), "=r"(b) : "r"(sa));
}
__device__ __forceinline__ void cp16(void* sdst, const void* g) {
    uint32_t sa = (uint32_t)__cvta_generic_to_shared(sdst);
    asm volatile("cp.async.cg.shared.global [%0], [%1], 16;" :: "r"(sa), "l"(g) : "memory");
}
#define CP_COMMIT() asm volatile("cp.async.commit_group;" ::: "memory")
#define CP_WAIT0()  asm volatile("cp.async.wait_group 0;" ::: "memory")

// ---------------- prep ----------------
__global__ void prep_kernel(const float* __restrict__ e_in,
                            const float* __restrict__ bn_in,
                            const float* __restrict__ b_in,
                            const float* __restrict__ e_mid,
                            const float* __restrict__ bn_mid,
                            const float* __restrict__ b_mid,
                            const float* __restrict__ e_out) {
    int t = threadIdx.x;
    if (t < 160) {
        int l = t >> 4, i = t & 15;
        const float* e = (l == 0) ? e_in : ((l <= 8) ? (e_mid + (l - 1) * 256) : e_out);
        unsigned int m = c_maskrow[i];
        float mx = -3.4e38f;
        for (int j = 0; j < 16; j++)
            if ((m >> j) & 1u) mx = fmaxf(mx, e[i * 16 + j]);
        float a[16]; float s = 0.f;
        for (int j = 0; j < 16; j++) {
            float v = ((m >> j) & 1u) ? expf(e[i * 16 + j] - mx) : 0.f;
            a[j] = v; s += v;
        }
        float inv = 1.f / s;
        g_d[l][i] = a[i] * inv;
        for (int j = 0; j < 16; j++)
            g_Aoff[l][i][j] = (j == i) ? 0.f : a[j] * inv;
    }
    for (int idx = t; idx < 9 * HID; idx += blockDim.x) {
        int lb = idx >> 7, f = idx & 127;
        float gamma, beta, mean, var, bias;
        if (lb == 0) {
            gamma = bn_in[f]; beta = bn_in[128 + f];
            mean = bn_in[256 + f]; var = bn_in[384 + f];
            bias = b_in[f];
        } else {
            const float* base = bn_mid + (lb - 1) * 512;
            gamma = base[f]; beta = base[128 + f];
            mean = base[256 + f]; var = base[384 + f];
            bias = b_mid[(lb - 1) * 128 + f];
        }
        float sc = gamma * rsqrtf(var + 1e-5f);
        g_scale[lb][f] = sc;
        g_shift[lb][f] = beta - mean * sc + bias * sc;
    }
}

// weight fragment shuffle: one thread per 8B unit (2 regs x 2 halves)
__global__ void wprep_kernel(const float* __restrict__ Wmid) {
    int idx = blockIdx.x * blockDim.x + threadIdx.x;
    if (idx >= 8 * 8 * 2 * 2 * 16 * 32) return;
    int lane = idx & 31;
    int n8 = (idx >> 5) & 15;
    int plane = (idx >> 9) & 1;
    int pair = (idx >> 10) & 1;
    int sc = (idx >> 11) & 7;
    int l = idx >> 14;
    int n = n8 * 8 + (lane >> 2);
    int chunk = pair ? (sc + 8) : sc;
    __half out[4];
#pragma unroll
    for (int r = 0; r < 2; r++)
#pragma unroll
        for (int h = 0; h < 2; h++) {
            int klocal = (lane & 3) * 2 + h + r * 8;
            int kk = chunk * 16 + klocal;
            float v = (kk < 128) ? Wmid[((l * 2 + 0) * 128 + kk) * 128 + n]
                                 : Wmid[((l * 2 + 1) * 128 + (kk - 128)) * 128 + n];
            __half hi = __float2half_rn(v);
            out[r * 2 + h] = plane ? __float2half_rn(v - __half2float(hi)) : hi;
        }
    *(uint64_t*)&g_Bfrag[(size_t)idx * 4] = *(uint64_t*)out;
}

// ---------------- input layer ----------------
__global__ void __launch_bounds__(128) in_kernel(const float* __restrict__ x,
                                                 const float* __restrict__ Win) {
    __shared__ float xs[16][2];
    __shared__ float sd[16];
    __shared__ float sAoff[16][16];
    int b = blockIdx.x, t = threadIdx.x;
    if (t < 32) ((float*)xs)[t] = x[b * 32 + t];
    if (t < 16) sd[t] = g_d[0][t];
    for (int e = t; e < 256; e += 128)
        sAoff[e >> 4][e & 15] = g_Aoff[0][e >> 4][e & 15];
    __syncthreads();
    int f = t;
    float w00 = Win[f], w01 = Win[128 + f], w10 = Win[256 + f], w11 = Win[384 + f];
    float q[16];
#pragma unroll
    for (int j = 0; j < 16; j++) q[j] = xs[j][0] * w10 + xs[j][1] * w11;
    float sc = g_scale[0][f], sh = g_shift[0][f];
#pragma unroll
    for (int i = 0; i < 16; i++) {
        float o = sd[i] * (xs[i][0] * w00 + xs[i][1] * w01);
#pragma unroll
        for (int j = 0; j < 16; j++) o += sAoff[i][j] * q[j];
        g_h[(b * 16 + i) * HID + f] = fmaxf(o * sc + sh, 0.f);
    }
}

// ---------------- mid layer via HMMA ----------------
#define XS_STR 20
#define A_STR 24
struct MidSm {
    float Xs[2][128][XS_STR];                 // 20480 B
    __half Bs[2][2][2][16][32][4];            // 32768 B
    __half Ah[2][128][A_STR];                 // 12288 B
    __half Al[2][128][A_STR];                 // 12288 B
    float sA[16][17];
    float sd[16];
    float scl[128], shf[128];
};

__global__ void __launch_bounds__(256, 2)
mid_mma(const float* __restrict__ X, float* __restrict__ Y,
        const float* __restrict__ R, const __half* __restrict__ Bf, int layer) {
    extern __shared__ __align__(16) char smraw[];
    MidSm& S = *reinterpret_cast<MidSm*>(smraw);
    const int t = threadIdx.x, lane = t & 31, warp = t >> 5;
    const int wm = warp & 3, wn = warp >> 2;      // 4 m-warps x 2 n-warps
    const int m0 = blockIdx.x * 128;

    if (t < 256) S.sA[t >> 4][t & 15] = g_Aoff[layer][t >> 4][t & 15];
    if (t < 16) S.sd[t] = g_d[layer][t];
    if (t < 128) { S.scl[t] = g_scale[layer][t]; S.shf[t] = g_shift[layer][t]; }

    // prefetch super-chunk 0
    {
        int u0 = t, u1 = t + 256;
        cp16(&S.Xs[0][u0 >> 2][(u0 & 3) * 4], X + (m0 + (u0 >> 2)) * HID + (u0 & 3) * 4);
        cp16(&S.Xs[0][u1 >> 2][(u1 & 3) * 4], X + (m0 + (u1 >> 2)) * HID + (u1 & 3) * 4);
#pragma unroll
        for (int i = 0; i < 4; i++) {
            int u = t + i * 256;
            cp16(((char*)S.Bs[0]) + u * 16, Bf + (size_t)u * 8);
        }
        CP_COMMIT();
    }

    float acc[2][8][4];
#pragma unroll
    for (int a = 0; a < 2; a++)
#pragma unroll
        for (int b = 0; b < 8; b++)
#pragma unroll
            for (int c = 0; c < 4; c++) acc[a][b][c] = 0.f;

    const uint32_t smbase = (uint32_t)__cvta_generic_to_shared(&S);
    const uint32_t AhOff = (uint32_t)((char*)&S.Ah[0][0][0] - (char*)&S);
    const uint32_t AlOff = (uint32_t)((char*)&S.Al[0][0][0] - (char*)&S);
    const uint32_t BsOff = (uint32_t)((char*)&S.Bs[0][0][0][0][0][0] - (char*)&S);

    for (int sc = 0; sc < 8; sc++) {
        int buf = sc & 1;
        CP_WAIT0();
        __syncthreads();
        if (sc < 7) {
            int nb = buf ^ 1, k0 = (sc + 1) * 16;
            int u0 = t, u1 = t + 256;
            cp16(&S.Xs[nb][u0 >> 2][(u0 & 3) * 4], X + (m0 + (u0 >> 2)) * HID + k0 + (u0 & 3) * 4);
            cp16(&S.Xs[nb][u1 >> 2][(u1 & 3) * 4], X + (m0 + (u1 >> 2)) * HID + k0 + (u1 & 3) * 4);
#pragma unroll
            for (int i = 0; i < 4; i++) {
                int u = t + i * 256;
                cp16(((char*)S.Bs[nb]) + u * 16, Bf + (size_t)(sc + 1) * 8192 + (size_t)u * 8);
            }
            CP_COMMIT();
        }
        // premix: thread -> (row r, kb = 0 or 8)
        {
            int r = t >> 1, kb = (t & 1) * 8;
            int i = r & 15, rb = r & ~15;
            float d = S.sd[i];
            const float* xrow = &S.Xs[buf][r][kb];
#pragma unroll
            for (int q = 0; q < 8; q++) {
                float u = d * xrow[q];
                __half uh = __float2half_rn(u);
                S.Ah[0][r][kb + q] = uh;
                S.Al[0][r][kb + q] = __float2half_rn(u - __half2float(uh));
            }
            unsigned long long vacc[4];
#pragma unroll
            for (int q = 0; q < 4; q++) vacc[q] = pack2(0.f, 0.f);
#pragma unroll
            for (int j = 0; j < 16; j++) {
                float aij = S.sA[i][j];
                unsigned long long ap = pack2(aij, aij);
                const unsigned long long* xr = (const unsigned long long*)&S.Xs[buf][rb + j][kb];
#pragma unroll
                for (int q = 0; q < 4; q++) vacc[q] = ffma2(ap, xr[q], vacc[q]);
            }
#pragma unroll
            for (int q = 0; q < 4; q++) {
                float v0, v1; unpack2(vacc[q], v0, v1);
                __half h0 = __float2half_rn(v0), h1 = __float2half_rn(v1);
                S.Ah[1][r][kb + q * 2] = h0;
                S.Ah[1][r][kb + q * 2 + 1] = h1;
                S.Al[1][r][kb + q * 2] = __float2half_rn(v0 - __half2float(h0));
                S.Al[1][r][kb + q * 2 + 1] = __float2half_rn(v1 - __half2float(h1));
            }
        }
        __syncthreads();
        // mma: pair 0 = U chunk, pair 1 = V chunk
#pragma unroll
        for (int pr = 0; pr < 2; pr++) {
            uint32_t ah[2][4], al[2][4];
            int lr = lane & 7, sel = lane >> 3;
            int rofs = (sel & 1) * 8 + lr, cofs = (sel >> 1) * 8;
#pragma unroll
            for (int mf = 0; mf < 2; mf++) {
                int row = wm * 32 + mf * 16 + rofs;
                uint32_t ao = (uint32_t)((pr * 128 + row) * A_STR + cofs) * 2;
                ldm4(ah[mf], smbase + AhOff + ao);
                ldm4(al[mf], smbase + AlOff + ao);
            }
#pragma unroll
            for (int nf = 0; nf < 8; nf++) {
                uint32_t bb = smbase + BsOff + (uint32_t)buf * 16384 +
                              (uint32_t)pr * 8192 + (uint32_t)(wn * 8 + nf) * 256 +
                              (uint32_t)lane * 8;
                uint32_t bh0, bh1, bl0, bl1;
                lds64(bh0, bh1, bb);
                lds64(bl0, bl1, bb + 4096);
#pragma unroll
                for (int mf = 0; mf < 2; mf++) {
                    mma16816(acc[mf][nf], ah[mf], bh0, bh1);
                    mma16816(acc[mf][nf], al[mf], bh0, bh1);
                    mma16816(acc[mf][nf], ah[mf], bl0, bl1);
                }
            }
        }
    }
    // epilogue
#pragma unroll
    for (int mf = 0; mf < 2; mf++) {
        int r0 = m0 + wm * 32 + mf * 16 + (lane >> 2);
#pragma unroll
        for (int nf = 0; nf < 8; nf++) {
            int cg = wn * 64 + nf * 8 + (lane & 3) * 2;
            float s0 = S.scl[cg], s1 = S.scl[cg + 1];
            float h0 = S.shf[cg], h1 = S.shf[cg + 1];
            float y0 = fmaxf(acc[mf][nf][0] * s0 + h0, 0.f);
            float y1 = fmaxf(acc[mf][nf][1] * s1 + h1, 0.f);
            float y2 = fmaxf(acc[mf][nf][2] * s0 + h0, 0.f);
            float y3 = fmaxf(acc[mf][nf][3] * s1 + h1, 0.f);
            if (R) {
                y0 += R[r0 * HID + cg];       y1 += R[r0 * HID + cg + 1];
                y2 += R[(r0 + 8) * HID + cg]; y3 += R[(r0 + 8) * HID + cg + 1];
            }
            float2 v0; v0.x = y0; v0.y = y1;
            float2 v1; v1.x = y2; v1.y = y3;
            *(float2*)&Y[r0 * HID + cg] = v0;
            *(float2*)&Y[(r0 + 8) * HID + cg] = v1;
        }
    }
}

// ---------------- output layer + MDN ----------------
__global__ void __launch_bounds__(128) out_kernel(const float* __restrict__ Wout,
                                                  const float* __restrict__ bout,
                                                  float* __restrict__ out) {
    __shared__ float hb[16][132];
    __shared__ float Wsf[256 * 26];
    __shared__ float ps[50][17];
    __shared__ float sd[16];
    __shared__ float sAoff[16][16];
    int b = blockIdx.x, t = threadIdx.x;
    if (t < 16) sd[t] = g_d[9][t];
    for (int e = t; e < 256; e += 128)
        sAoff[e >> 4][e & 15] = g_Aoff[9][e >> 4][e & 15];
    for (int i = 0; i < 16; i++)
        hb[i][t] = g_h[(b * 16 + i) * HID + t];
    for (int idx = t; idx < 6400; idx += 128) {
        int s = idx / 3200;
        int r = idx - s * 3200;
        int k = r / 25;
        int c = r - k * 25;
        Wsf[(s * 128 + k) * 26 + c] = Wout[idx];
    }
    __syncthreads();
    int i = t >> 3, g = t & 7;
    float acc[7]; int off[7], uu[7]; int nq = 0;
    for (int u = g; u < 50; u += 8) {
        int sel = u / 25, c = u - sel * 25;
        off[nq] = sel * (128 * 26) + c;
        uu[nq] = u; acc[nq] = 0.f; nq++;
    }
    for (int k = 0; k < HID; k++) {
        float h = hb[i][k];
        int kb = k * 26;
#pragma unroll
        for (int q = 0; q < 7; q++)
            if (q < nq) acc[q] += h * Wsf[off[q] + kb];
    }
#pragma unroll
    for (int q = 0; q < 7; q++)
        if (q < nq) ps[uu[q]][i] = acc[q];
    __syncthreads();
    for (int e = t; e < 400; e += 128) {
        int i2 = e / 25, c = e - i2 * 25;
        float o = sd[i2] * ps[c][i2] + bout[c];
#pragma unroll
        for (int j = 0; j < 16; j++) o += sAoff[i2][j] * ps[25 + c][j];
        int row = b * 16 + i2;
        if (c < 15) {
            out[row * 15 + c] = tanhf(o);
        } else if (c < 20) {
            float s = (o > 0.f) ? (o + 1.f) : expf(o);
            out[BATCH * NJ * 15 + row * 5 + (c - 15)] = fmaxf(s, 1e-10f);
        } else {
            out[BATCH * NJ * 20 + row * 5 + (c - 20)] = o;
        }
    }
}

extern "C" void kernel_launch(void* const* d_in, const int* in_sizes, int n_in,
                              void* d_out, int out_size) {
    const float* x      = (const float*)d_in[0];
    const float* W_in   = (const float*)d_in[1];
    const float* e_in   = (const float*)d_in[2];
    const float* b_in   = (const float*)d_in[3];
    const float* bn_in  = (const float*)d_in[4];
    const float* W_mid  = (const float*)d_in[5];
    const float* e_mid  = (const float*)d_in[6];
    const float* b_mid  = (const float*)d_in[7];
    const float* bn_mid = (const float*)d_in[8];
    const float* W_out  = (const float*)d_in[9];
    const float* e_out  = (const float*)d_in[10];
    const float* b_out  = (const float*)d_in[11];
    float* out = (float*)d_out;

    static int smem_set = 0;
    if (!smem_set) {
        cudaFuncSetAttribute(mid_mma, cudaFuncAttributeMaxDynamicSharedMemorySize,
                             (int)sizeof(MidSm));
        smem_set = 1;
    }

    prep_kernel<<<1, 256>>>(e_in, bn_in, b_in, e_mid, bn_mid, b_mid, e_out);
    wprep_kernel<<<2048, 256>>>(W_mid);
    in_kernel<<<BATCH, 128>>>(x, W_in);

    const int nblk = MROWS / 128;
    const size_t smb = sizeof(MidSm);
    __half* bfh = nullptr;
    cudaGetSymbolAddress((void**)&bfh, g_Bfrag);
    float *gh = nullptr, *gt = nullptr;
    cudaGetSymbolAddress((void**)&gh, g_h);
    cudaGetSymbolAddress((void**)&gt, g_t);
    for (int p = 0; p < 4; p++) {
        mid_mma<<<nblk, 256, smb>>>(gh, gt, nullptr, bfh + (size_t)(2 * p) * 65536, 1 + 2 * p);
        mid_mma<<<nblk, 256, smb>>>(gt, gh, gh, bfh + (size_t)(2 * p + 1) * 65536, 2 + 2 * p);
    }
    out_kernel<<<BATCH, 128>>>(W_out, b_out, out);
}

// round 5
// speedup vs baseline: 2.3713x; 1.5515x over previous
#include <cuda_runtime.h>
#include <cuda_fp16.h>
#include <math.h>
#include <stdint.h>

#define BATCH 16384
#define NJ 16
#define HID 128
#define MROWS (BATCH*NJ)

__constant__ unsigned int c_maskrow[16] = {
    0x0093u, 0x0007u, 0x000Eu, 0x000Cu,
    0x0031u, 0x0070u, 0x0060u, 0x0181u,
    0x4B80u, 0x0700u, 0x0600u, 0x1900u,
    0x3800u, 0x3000u, 0xC100u, 0xC000u
};

__device__ float g_h[MROWS * HID];
__device__ float g_t[MROWS * HID];
__device__ float g_d[10][16];
__device__ float g_Aoff[10][16][16];
__device__ float g_scale[9][HID];
__device__ float g_shift[9][HID];
// weight fragments: [l][sc=8][pair=2][plane=2][n8=16][lane=32][4 halves]
__device__ __half g_Bfrag[8 * 8 * 2 * 2 * 16 * 32 * 4];

__device__ __forceinline__ unsigned long long pack2(float x, float y) {
    unsigned long long r;
    asm("mov.b64 %0, {%1,%2};" : "=l"(r) : "f"(x), "f"(y));
    return r;
}
__device__ __forceinline__ void unpack2(unsigned long long v, float &x, float &y) {
    asm("mov.b64 {%0,%1}, %2;" : "=f"(x), "=f"(y) : "l"(v));
}
__device__ __forceinline__ unsigned long long ffma2(unsigned long long a,
                                                    unsigned long long b,
                                                    unsigned long long c) {
    unsigned long long d;
    asm("fma.rn.f32x2 %0, %1, %2, %3;" : "=l"(d) : "l"(a), "l"(b), "l"(c));
    return d;
}
__device__ __forceinline__ void mma16816(float* c, const uint32_t* a,
                                         uint32_t b0, uint32_t b1) {
    asm volatile(
        "mma.sync.aligned.m16n8k16.row.col.f32.f16.f16.f32 "
        "{%0,%1,%2,%3},{%4,%5,%6,%7},{%8,%9},{%0,%1,%2,%3};"
        : "+f"(c[0]), "+f"(c[1]), "+f"(c[2]), "+f"(c[3])
        : "r"(a[0]), "r"(a[1]), "r"(a[2]), "r"(a[3]), "r"(b0), "r"(b1));
}
__device__ __forceinline__ void ldm4(uint32_t* d, uint32_t sa) {
    asm volatile("ldmatrix.sync.aligned.m8n8.x4.shared.b16 {%0,%1,%2,%3}, [%4];"
                 : "=r"(d[0]), "=r"(d[1]), "=r"(d[2]), "=r"(d[3]) : "r"(sa));
}
__device__ __forceinline__ void lds64(uint32_t& a, uint32_t& b, uint32_t sa) {
    asm volatile("ld.shared.v2.b32 {%0,%1}, [%2];" : "=r"(a), "=r"(b) : "r"(sa));
}
__device__ __forceinline__ void cp16(void* sdst, const void* g) {
    uint32_t sa = (uint32_t)__cvta_generic_to_shared(sdst);
    asm volatile("cp.async.cg.shared.global [%0], [%1], 16;" :: "r"(sa), "l"(g) : "memory");
}
#define CP_COMMIT() asm volatile("cp.async.commit_group;" ::: "memory")
#define CP_WAIT0()  asm volatile("cp.async.wait_group 0;" ::: "memory")

// ---------------- prep ----------------
__global__ void prep_kernel(const float* __restrict__ e_in,
                            const float* __restrict__ bn_in,
                            const float* __restrict__ b_in,
                            const float* __restrict__ e_mid,
                            const float* __restrict__ bn_mid,
                            const float* __restrict__ b_mid,
                            const float* __restrict__ e_out) {
    int t = threadIdx.x;
    if (t < 160) {
        int l = t >> 4, i = t & 15;
        const float* e = (l == 0) ? e_in : ((l <= 8) ? (e_mid + (l - 1) * 256) : e_out);
        unsigned int m = c_maskrow[i];
        float mx = -3.4e38f;
        for (int j = 0; j < 16; j++)
            if ((m >> j) & 1u) mx = fmaxf(mx, e[i * 16 + j]);
        float a[16]; float s = 0.f;
        for (int j = 0; j < 16; j++) {
            float v = ((m >> j) & 1u) ? expf(e[i * 16 + j] - mx) : 0.f;
            a[j] = v; s += v;
        }
        float inv = 1.f / s;
        g_d[l][i] = a[i] * inv;
        for (int j = 0; j < 16; j++)
            g_Aoff[l][i][j] = (j == i) ? 0.f : a[j] * inv;
    }
    for (int idx = t; idx < 9 * HID; idx += blockDim.x) {
        int lb = idx >> 7, f = idx & 127;
        float gamma, beta, mean, var, bias;
        if (lb == 0) {
            gamma = bn_in[f]; beta = bn_in[128 + f];
            mean = bn_in[256 + f]; var = bn_in[384 + f];
            bias = b_in[f];
        } else {
            const float* base = bn_mid + (lb - 1) * 512;
            gamma = base[f]; beta = base[128 + f];
            mean = base[256 + f]; var = base[384 + f];
            bias = b_mid[(lb - 1) * 128 + f];
        }
        float sc = gamma * rsqrtf(var + 1e-5f);
        g_scale[lb][f] = sc;
        g_shift[lb][f] = beta - mean * sc + bias * sc;
    }
}

// weight fragment shuffle: one thread per 8B unit (2 regs x 2 halves)
__global__ void wprep_kernel(const float* __restrict__ Wmid) {
    int idx = blockIdx.x * blockDim.x + threadIdx.x;
    if (idx >= 8 * 8 * 2 * 2 * 16 * 32) return;
    int lane = idx & 31;
    int n8 = (idx >> 5) & 15;
    int plane = (idx >> 9) & 1;
    int pair = (idx >> 10) & 1;
    int sc = (idx >> 11) & 7;
    int l = idx >> 14;
    int n = n8 * 8 + (lane >> 2);
    int chunk = pair ? (sc + 8) : sc;
    __half out[4];
#pragma unroll
    for (int r = 0; r < 2; r++)
#pragma unroll
        for (int h = 0; h < 2; h++) {
            int klocal = (lane & 3) * 2 + h + r * 8;
            int kk = chunk * 16 + klocal;
            float v = (kk < 128) ? Wmid[((l * 2 + 0) * 128 + kk) * 128 + n]
                                 : Wmid[((l * 2 + 1) * 128 + (kk - 128)) * 128 + n];
            __half hi = __float2half_rn(v);
            out[r * 2 + h] = plane ? __float2half_rn(v - __half2float(hi)) : hi;
        }
    *(uint64_t*)&g_Bfrag[(size_t)idx * 4] = *(uint64_t*)out;
}

// ---------------- input layer ----------------
__global__ void __launch_bounds__(128) in_kernel(const float* __restrict__ x,
                                                 const float* __restrict__ Win) {
    __shared__ float xs[16][2];
    __shared__ float sd[16];
    __shared__ float sAoff[16][16];
    int b = blockIdx.x, t = threadIdx.x;
    if (t < 32) ((float*)xs)[t] = x[b * 32 + t];
    if (t < 16) sd[t] = g_d[0][t];
    for (int e = t; e < 256; e += 128)
        sAoff[e >> 4][e & 15] = g_Aoff[0][e >> 4][e & 15];
    __syncthreads();
    int f = t;
    float w00 = Win[f], w01 = Win[128 + f], w10 = Win[256 + f], w11 = Win[384 + f];
    float q[16];
#pragma unroll
    for (int j = 0; j < 16; j++) q[j] = xs[j][0] * w10 + xs[j][1] * w11;
    float sc = g_scale[0][f], sh = g_shift[0][f];
#pragma unroll
    for (int i = 0; i < 16; i++) {
        float o = sd[i] * (xs[i][0] * w00 + xs[i][1] * w01);
#pragma unroll
        for (int j = 0; j < 16; j++) o += sAoff[i][j] * q[j];
        g_h[(b * 16 + i) * HID + f] = fmaxf(o * sc + sh, 0.f);
    }
}

// ---------------- mid layer via HMMA ----------------
#define XS_STR 20
#define A_STR 24
struct MidSm {
    float Xs[2][128][XS_STR];                 // 20480 B
    __half Bs[2][2][2][16][32][4];            // 32768 B
    __half Ah[2][128][A_STR];                 // 12288 B
    __half Al[2][128][A_STR];                 // 12288 B
    float sA[16][17];
    float sd[16];
    float scl[128], shf[128];
};

__global__ void __launch_bounds__(256, 2)
mid_mma(const float* __restrict__ X, float* __restrict__ Y,
        const float* __restrict__ R, const __half* __restrict__ Bf, int layer) {
    extern __shared__ __align__(16) char smraw[];
    MidSm& S = *reinterpret_cast<MidSm*>(smraw);
    const int t = threadIdx.x, lane = t & 31, warp = t >> 5;
    const int wm = warp & 3, wn = warp >> 2;      // 4 m-warps x 2 n-warps
    const int m0 = blockIdx.x * 128;

    if (t < 256) S.sA[t >> 4][t & 15] = g_Aoff[layer][t >> 4][t & 15];
    if (t < 16) S.sd[t] = g_d[layer][t];
    if (t < 128) { S.scl[t] = g_scale[layer][t]; S.shf[t] = g_shift[layer][t]; }

    // prefetch super-chunk 0
    {
        int u0 = t, u1 = t + 256;
        cp16(&S.Xs[0][u0 >> 2][(u0 & 3) * 4], X + (m0 + (u0 >> 2)) * HID + (u0 & 3) * 4);
        cp16(&S.Xs[0][u1 >> 2][(u1 & 3) * 4], X + (m0 + (u1 >> 2)) * HID + (u1 & 3) * 4);
#pragma unroll
        for (int i = 0; i < 4; i++) {
            int u = t + i * 256;
            cp16(((char*)S.Bs[0]) + u * 16, Bf + (size_t)u * 8);
        }
        CP_COMMIT();
    }

    float acc[2][8][4];
#pragma unroll
    for (int a = 0; a < 2; a++)
#pragma unroll
        for (int b = 0; b < 8; b++)
#pragma unroll
            for (int c = 0; c < 4; c++) acc[a][b][c] = 0.f;

    const uint32_t smbase = (uint32_t)__cvta_generic_to_shared(&S);
    const uint32_t AhOff = (uint32_t)((char*)&S.Ah[0][0][0] - (char*)&S);
    const uint32_t AlOff = (uint32_t)((char*)&S.Al[0][0][0] - (char*)&S);
    const uint32_t BsOff = (uint32_t)((char*)&S.Bs[0][0][0][0][0][0] - (char*)&S);

    for (int sc = 0; sc < 8; sc++) {
        int buf = sc & 1;
        CP_WAIT0();
        __syncthreads();
        if (sc < 7) {
            int nb = buf ^ 1, k0 = (sc + 1) * 16;
            int u0 = t, u1 = t + 256;
            cp16(&S.Xs[nb][u0 >> 2][(u0 & 3) * 4], X + (m0 + (u0 >> 2)) * HID + k0 + (u0 & 3) * 4);
            cp16(&S.Xs[nb][u1 >> 2][(u1 & 3) * 4], X + (m0 + (u1 >> 2)) * HID + k0 + (u1 & 3) * 4);
#pragma unroll
            for (int i = 0; i < 4; i++) {
                int u = t + i * 256;
                cp16(((char*)S.Bs[nb]) + u * 16, Bf + (size_t)(sc + 1) * 8192 + (size_t)u * 8);
            }
            CP_COMMIT();
        }
        // premix: thread -> (row r, kb = 0 or 8)
        {
            int r = t >> 1, kb = (t & 1) * 8;
            int i = r & 15, rb = r & ~15;
            float d = S.sd[i];
            const float* xrow = &S.Xs[buf][r][kb];
#pragma unroll
            for (int q = 0; q < 8; q++) {
                float u = d * xrow[q];
                __half uh = __float2half_rn(u);
                S.Ah[0][r][kb + q] = uh;
                S.Al[0][r][kb + q] = __float2half_rn(u - __half2float(uh));
            }
            unsigned long long vacc[4];
#pragma unroll
            for (int q = 0; q < 4; q++) vacc[q] = pack2(0.f, 0.f);
#pragma unroll
            for (int j = 0; j < 16; j++) {
                float aij = S.sA[i][j];
                unsigned long long ap = pack2(aij, aij);
                const unsigned long long* xr = (const unsigned long long*)&S.Xs[buf][rb + j][kb];
#pragma unroll
                for (int q = 0; q < 4; q++) vacc[q] = ffma2(ap, xr[q], vacc[q]);
            }
#pragma unroll
            for (int q = 0; q < 4; q++) {
                float v0, v1; unpack2(vacc[q], v0, v1);
                __half h0 = __float2half_rn(v0), h1 = __float2half_rn(v1);
                S.Ah[1][r][kb + q * 2] = h0;
                S.Ah[1][r][kb + q * 2 + 1] = h1;
                S.Al[1][r][kb + q * 2] = __float2half_rn(v0 - __half2float(h0));
                S.Al[1][r][kb + q * 2 + 1] = __float2half_rn(v1 - __half2float(h1));
            }
        }
        __syncthreads();
        // mma: pair 0 = U chunk, pair 1 = V chunk
#pragma unroll
        for (int pr = 0; pr < 2; pr++) {
            uint32_t ah[2][4], al[2][4];
            int lr = lane & 7, sel = lane >> 3;
            int rofs = (sel & 1) * 8 + lr, cofs = (sel >> 1) * 8;
#pragma unroll
            for (int mf = 0; mf < 2; mf++) {
                int row = wm * 32 + mf * 16 + rofs;
                uint32_t ao = (uint32_t)((pr * 128 + row) * A_STR + cofs) * 2;
                ldm4(ah[mf], smbase + AhOff + ao);
                ldm4(al[mf], smbase + AlOff + ao);
            }
#pragma unroll
            for (int nf = 0; nf < 8; nf++) {
                uint32_t bb = smbase + BsOff + (uint32_t)buf * 16384 +
                              (uint32_t)pr * 8192 + (uint32_t)(wn * 8 + nf) * 256 +
                              (uint32_t)lane * 8;
                uint32_t bh0, bh1, bl0, bl1;
                lds64(bh0, bh1, bb);
                lds64(bl0, bl1, bb + 4096);
#pragma unroll
                for (int mf = 0; mf < 2; mf++) {
                    mma16816(acc[mf][nf], ah[mf], bh0, bh1);
                    mma16816(acc[mf][nf], al[mf], bh0, bh1);
                    mma16816(acc[mf][nf], ah[mf], bl0, bl1);
                }
            }
        }
    }
    // epilogue
#pragma unroll
    for (int mf = 0; mf < 2; mf++) {
        int r0 = m0 + wm * 32 + mf * 16 + (lane >> 2);
#pragma unroll
        for (int nf = 0; nf < 8; nf++) {
            int cg = wn * 64 + nf * 8 + (lane & 3) * 2;
            float s0 = S.scl[cg], s1 = S.scl[cg + 1];
            float h0 = S.shf[cg], h1 = S.shf[cg + 1];
            float y0 = fmaxf(acc[mf][nf][0] * s0 + h0, 0.f);
            float y1 = fmaxf(acc[mf][nf][1] * s1 + h1, 0.f);
            float y2 = fmaxf(acc[mf][nf][2] * s0 + h0, 0.f);
            float y3 = fmaxf(acc[mf][nf][3] * s1 + h1, 0.f);
            if (R) {
                y0 += R[r0 * HID + cg];       y1 += R[r0 * HID + cg + 1];
                y2 += R[(r0 + 8) * HID + cg]; y3 += R[(r0 + 8) * HID + cg + 1];
            }
            float2 v0; v0.x = y0; v0.y = y1;
            float2 v1; v1.x = y2; v1.y = y3;
            *(float2*)&Y[r0 * HID + cg] = v0;
            *(float2*)&Y[(r0 + 8) * HID + cg] = v1;
        }
    }
}

// ---------------- output layer + MDN ----------------
__global__ void __launch_bounds__(128) out_kernel(const float* __restrict__ Wout,
                                                  const float* __restrict__ bout,
                                                  float* __restrict__ out) {
    __shared__ float hb[16][132];
    __shared__ float Wsf[256 * 26];
    __shared__ float ps[50][17];
    __shared__ float sd[16];
    __shared__ float sAoff[16][16];
    int b = blockIdx.x, t = threadIdx.x;
    if (t < 16) sd[t] = g_d[9][t];
    for (int e = t; e < 256; e += 128)
        sAoff[e >> 4][e & 15] = g_Aoff[9][e >> 4][e & 15];
    for (int i = 0; i < 16; i++)
        hb[i][t] = g_h[(b * 16 + i) * HID + t];
    for (int idx = t; idx < 6400; idx += 128) {
        int s = idx / 3200;
        int r = idx - s * 3200;
        int k = r / 25;
        int c = r - k * 25;
        Wsf[(s * 128 + k) * 26 + c] = Wout[idx];
    }
    __syncthreads();
    int i = t >> 3, g = t & 7;
    float acc[7]; int off[7], uu[7]; int nq = 0;
    for (int u = g; u < 50; u += 8) {
        int sel = u / 25, c = u - sel * 25;
        off[nq] = sel * (128 * 26) + c;
        uu[nq] = u; acc[nq] = 0.f; nq++;
    }
    for (int k = 0; k < HID; k++) {
        float h = hb[i][k];
        int kb = k * 26;
#pragma unroll
        for (int q = 0; q < 7; q++)
            if (q < nq) acc[q] += h * Wsf[off[q] + kb];
    }
#pragma unroll
    for (int q = 0; q < 7; q++)
        if (q < nq) ps[uu[q]][i] = acc[q];
    __syncthreads();
    for (int e = t; e < 400; e += 128) {
        int i2 = e / 25, c = e - i2 * 25;
        float o = sd[i2] * ps[c][i2] + bout[c];
#pragma unroll
        for (int j = 0; j < 16; j++) o += sAoff[i2][j] * ps[25 + c][j];
        int row = b * 16 + i2;
        if (c < 15) {
            out[row * 15 + c] = tanhf(o);
        } else if (c < 20) {
            float s = (o > 0.f) ? (o + 1.f) : expf(o);
            out[BATCH * NJ * 15 + row * 5 + (c - 15)] = fmaxf(s, 1e-10f);
        } else {
            out[BATCH * NJ * 20 + row * 5 + (c - 20)] = o;
        }
    }
}

extern "C" void kernel_launch(void* const* d_in, const int* in_sizes, int n_in,
                              void* d_out, int out_size) {
    const float* x      = (const float*)d_in[0];
    const float* W_in   = (const float*)d_in[1];
    const float* e_in   = (const float*)d_in[2];
    const float* b_in   = (const float*)d_in[3];
    const float* bn_in  = (const float*)d_in[4];
    const float* W_mid  = (const float*)d_in[5];
    const float* e_mid  = (const float*)d_in[6];
    const float* b_mid  = (const float*)d_in[7];
    const float* bn_mid = (const float*)d_in[8];
    const float* W_out  = (const float*)d_in[9];
    const float* e_out  = (const float*)d_in[10];
    const float* b_out  = (const float*)d_in[11];
    float* out = (float*)d_out;

    static int smem_set = 0;
    if (!smem_set) {
        cudaFuncSetAttribute(mid_mma, cudaFuncAttributeMaxDynamicSharedMemorySize,
                             (int)sizeof(MidSm));
        smem_set = 1;
    }

    prep_kernel<<<1, 256>>>(e_in, bn_in, b_in, e_mid, bn_mid, b_mid, e_out);
    wprep_kernel<<<2048, 256>>>(W_mid);
    in_kernel<<<BATCH, 128>>>(x, W_in);

    const int nblk = MROWS / 128;
    const size_t smb = sizeof(MidSm);
    __half* bfh = nullptr;
    cudaGetSymbolAddress((void**)&bfh, g_Bfrag);
    float *gh = nullptr, *gt = nullptr;
    cudaGetSymbolAddress((void**)&gh, g_h);
    cudaGetSymbolAddress((void**)&gt, g_t);
    for (int p = 0; p < 4; p++) {
        mid_mma<<<nblk, 256, smb>>>(gh, gt, nullptr, bfh + (size_t)(2 * p) * 65536, 1 + 2 * p);
        mid_mma<<<nblk, 256, smb>>>(gt, gh, gh, bfh + (size_t)(2 * p + 1) * 65536, 2 + 2 * p);
    }
    out_kernel<<<BATCH, 128>>>(W_out, b_out, out);
}

// round 7
// speedup vs baseline: 2.4168x; 1.0192x over previous
#include <cuda_runtime.h>
#include <cuda_fp16.h>
#include <math.h>
#include <stdint.h>

#define BATCH 16384
#define NJ 16
#define HID 128
#define MROWS (BATCH*NJ)

__constant__ unsigned int c_maskrow[16] = {
    0x0093u, 0x0007u, 0x000Eu, 0x000Cu,
    0x0031u, 0x0070u, 0x0060u, 0x0181u,
    0x4B80u, 0x0700u, 0x0600u, 0x1900u,
    0x3800u, 0x3000u, 0xC100u, 0xC000u
};

__device__ float g_h[MROWS * HID];
__device__ float g_t[MROWS * HID];
__device__ float g_d[10][16];
__device__ float g_Aoff[10][16][16];
__device__ float g_scale[9][HID];
__device__ float g_shift[9][HID];
// weight fragments: [l][sc=8][pair=2][plane=2][n8=16][lane=32][4 halves]
__device__ __half g_Bfrag[8 * 8 * 2 * 2 * 16 * 32 * 4];

__device__ __forceinline__ unsigned long long pack2(float x, float y) {
    unsigned long long r;
    asm("mov.b64 %0, {%1,%2};" : "=l"(r) : "f"(x), "f"(y));
    return r;
}
__device__ __forceinline__ void unpack2(unsigned long long v, float &x, float &y) {
    asm("mov.b64 {%0,%1}, %2;" : "=f"(x), "=f"(y) : "l"(v));
}
__device__ __forceinline__ unsigned long long ffma2(unsigned long long a,
                                                    unsigned long long b,
                                                    unsigned long long c) {
    unsigned long long d;
    asm("fma.rn.f32x2 %0, %1, %2, %3;" : "=l"(d) : "l"(a), "l"(b), "l"(c));
    return d;
}
__device__ __forceinline__ void mma16816(float* c, const uint32_t* a,
                                         uint32_t b0, uint32_t b1) {
    asm volatile(
        "mma.sync.aligned.m16n8k16.row.col.f32.f16.f16.f32 "
        "{%0,%1,%2,%3},{%4,%5,%6,%7},{%8,%9},{%0,%1,%2,%3};"
        : "+f"(c[0]), "+f"(c[1]), "+f"(c[2]), "+f"(c[3])
        : "r"(a[0]), "r"(a[1]), "r"(a[2]), "r"(a[3]), "r"(b0), "r"(b1));
}
__device__ __forceinline__ void ldm4(uint32_t* d, uint32_t sa) {
    asm volatile("ldmatrix.sync.aligned.m8n8.x4.shared.b16 {%0,%1,%2,%3}, [%4];"
                 : "=r"(d[0]), "=r"(d[1]), "=r"(d[2]), "=r"(d[3]) : "r"(sa));
}
__device__ __forceinline__ void lds64(uint32_t& a, uint32_t& b, uint32_t sa) {
    asm volatile("ld.shared.v2.b32 {%0,%1}, [%2];" : "=r"(a), "=r"(b) : "r"(sa));
}
__device__ __forceinline__ void cp16(void* sdst, const void* g) {
    uint32_t sa = (uint32_t)__cvta_generic_to_shared(sdst);
    asm volatile("cp.async.cg.shared.global [%0], [%1], 16;" :: "r"(sa), "l"(g) : "memory");
}
#define CP_COMMIT() asm volatile("cp.async.commit_group;" ::: "memory")
#define CP_WAIT0()  asm volatile("cp.async.wait_group 0;" ::: "memory")

// ---------------- prep ----------------
__global__ void prep_kernel(const float* __restrict__ e_in,
                            const float* __restrict__ bn_in,
                            const float* __restrict__ b_in,
                            const float* __restrict__ e_mid,
                            const float* __restrict__ bn_mid,
                            const float* __restrict__ b_mid,
                            const float* __restrict__ e_out) {
    int t = threadIdx.x;
    if (t < 160) {
        int l = t >> 4, i = t & 15;
        const float* e = (l == 0) ? e_in : ((l <= 8) ? (e_mid + (l - 1) * 256) : e_out);
        unsigned int m = c_maskrow[i];
        float mx = -3.4e38f;
        for (int j = 0; j < 16; j++)
            if ((m >> j) & 1u) mx = fmaxf(mx, e[i * 16 + j]);
        float a[16]; float s = 0.f;
        for (int j = 0; j < 16; j++) {
            float v = ((m >> j) & 1u) ? expf(e[i * 16 + j] - mx) : 0.f;
            a[j] = v; s += v;
        }
        float inv = 1.f / s;
        g_d[l][i] = a[i] * inv;
        for (int j = 0; j < 16; j++)
            g_Aoff[l][i][j] = (j == i) ? 0.f : a[j] * inv;
    }
    for (int idx = t; idx < 9 * HID; idx += blockDim.x) {
        int lb = idx >> 7, f = idx & 127;
        float gamma, beta, mean, var, bias;
        if (lb == 0) {
            gamma = bn_in[f]; beta = bn_in[128 + f];
            mean = bn_in[256 + f]; var = bn_in[384 + f];
            bias = b_in[f];
        } else {
            const float* base = bn_mid + (lb - 1) * 512;
            gamma = base[f]; beta = base[128 + f];
            mean = base[256 + f]; var = base[384 + f];
            bias = b_mid[(lb - 1) * 128 + f];
        }
        float sc = gamma * rsqrtf(var + 1e-5f);
        g_scale[lb][f] = sc;
        g_shift[lb][f] = beta - mean * sc + bias * sc;
    }
}

// weight fragment shuffle: one thread per 8B unit (2 regs x 2 halves)
__global__ void wprep_kernel(const float* __restrict__ Wmid) {
    int idx = blockIdx.x * blockDim.x + threadIdx.x;
    if (idx >= 8 * 8 * 2 * 2 * 16 * 32) return;
    int lane = idx & 31;
    int n8 = (idx >> 5) & 15;
    int plane = (idx >> 9) & 1;
    int pair = (idx >> 10) & 1;
    int sc = (idx >> 11) & 7;
    int l = idx >> 14;
    int n = n8 * 8 + (lane >> 2);
    int chunk = pair ? (sc + 8) : sc;
    __half out[4];
#pragma unroll
    for (int r = 0; r < 2; r++)
#pragma unroll
        for (int h = 0; h < 2; h++) {
            int klocal = (lane & 3) * 2 + h + r * 8;
            int kk = chunk * 16 + klocal;
            float v = (kk < 128) ? Wmid[((l * 2 + 0) * 128 + kk) * 128 + n]
                                 : Wmid[((l * 2 + 1) * 128 + (kk - 128)) * 128 + n];
            __half hi = __float2half_rn(v);
            out[r * 2 + h] = plane ? __float2half_rn(v - __half2float(hi)) : hi;
        }
    *(uint64_t*)&g_Bfrag[(size_t)idx * 4] = *(uint64_t*)out;
}

// ---------------- input layer: 2048 blocks x 256 thr, 128 rows/block ----------------
__global__ void __launch_bounds__(256) in_kernel(const float* __restrict__ x,
                                                 const float* __restrict__ Win) {
    __shared__ float xs[128][2];
    __shared__ float sA[16][16];
    __shared__ float sdv[16];
    __shared__ float scl[128], shf[128];
    const int t = threadIdx.x;
    const int m0 = blockIdx.x * 128;
    sA[t >> 4][t & 15] = g_Aoff[0][t >> 4][t & 15];
    if (t < 16) sdv[t] = g_d[0][t];
    if (t < 128) { scl[t] = g_scale[0][t]; shf[t] = g_shift[0][t]; }
    ((float*)xs)[t] = x[m0 * 2 + t];
    __syncthreads();
    const int f = t & 127, gh = t >> 7;
    float w00 = Win[f], w01 = Win[128 + f], w10 = Win[256 + f], w11 = Win[384 + f];
    float sc = scl[f], sh = shf[f];
    for (int gg = 0; gg < 4; gg++) {
        int g = gh * 4 + gg;
        float q[16];
#pragma unroll
        for (int j = 0; j < 16; j++)
            q[j] = xs[16 * g + j][0] * w10 + xs[16 * g + j][1] * w11;
#pragma unroll
        for (int i = 0; i < 16; i++) {
            float o = sdv[i] * (xs[16 * g + i][0] * w00 + xs[16 * g + i][1] * w01);
#pragma unroll
            for (int j = 0; j < 16; j++) o += sA[i][j] * q[j];
            g_h[(size_t)(m0 + 16 * g + i) * HID + f] = fmaxf(o * sc + sh, 0.f);
        }
    }
}

// ---------------- mid layer via HMMA (R5-verified, unchanged) ----------------
#define XS_STR 20
#define A_STR 24
struct MidSm {
    float Xs[2][128][XS_STR];
    __half Bs[2][2][2][16][32][4];
    __half Ah[2][128][A_STR];
    __half Al[2][128][A_STR];
    float sA[16][17];
    float sd[16];
    float scl[128], shf[128];
};

__global__ void __launch_bounds__(256, 2)
mid_mma(const float* __restrict__ X, float* __restrict__ Y,
        const float* __restrict__ R, const __half* __restrict__ Bf, int layer) {
    extern __shared__ __align__(16) char smraw[];
    MidSm& S = *reinterpret_cast<MidSm*>(smraw);
    const int t = threadIdx.x, lane = t & 31, warp = t >> 5;
    const int wm = warp & 3, wn = warp >> 2;
    const int m0 = blockIdx.x * 128;

    if (t < 256) S.sA[t >> 4][t & 15] = g_Aoff[layer][t >> 4][t & 15];
    if (t < 16) S.sd[t] = g_d[layer][t];
    if (t < 128) { S.scl[t] = g_scale[layer][t]; S.shf[t] = g_shift[layer][t]; }

    {
        int u0 = t, u1 = t + 256;
        cp16(&S.Xs[0][u0 >> 2][(u0 & 3) * 4], X + (m0 + (u0 >> 2)) * HID + (u0 & 3) * 4);
        cp16(&S.Xs[0][u1 >> 2][(u1 & 3) * 4], X + (m0 + (u1 >> 2)) * HID + (u1 & 3) * 4);
#pragma unroll
        for (int i = 0; i < 4; i++) {
            int u = t + i * 256;
            cp16(((char*)S.Bs[0]) + u * 16, Bf + (size_t)u * 8);
        }
        CP_COMMIT();
    }

    float acc[2][8][4];
#pragma unroll
    for (int a = 0; a < 2; a++)
#pragma unroll
        for (int b = 0; b < 8; b++)
#pragma unroll
            for (int c = 0; c < 4; c++) acc[a][b][c] = 0.f;

    const uint32_t smbase = (uint32_t)__cvta_generic_to_shared(&S);
    const uint32_t AhOff = (uint32_t)((char*)&S.Ah[0][0][0] - (char*)&S);
    const uint32_t AlOff = (uint32_t)((char*)&S.Al[0][0][0] - (char*)&S);
    const uint32_t BsOff = (uint32_t)((char*)&S.Bs[0][0][0][0][0][0] - (char*)&S);

    for (int sc = 0; sc < 8; sc++) {
        int buf = sc & 1;
        CP_WAIT0();
        __syncthreads();
        if (sc < 7) {
            int nb = buf ^ 1, k0 = (sc + 1) * 16;
            int u0 = t, u1 = t + 256;
            cp16(&S.Xs[nb][u0 >> 2][(u0 & 3) * 4], X + (m0 + (u0 >> 2)) * HID + k0 + (u0 & 3) * 4);
            cp16(&S.Xs[nb][u1 >> 2][(u1 & 3) * 4], X + (m0 + (u1 >> 2)) * HID + k0 + (u1 & 3) * 4);
#pragma unroll
            for (int i = 0; i < 4; i++) {
                int u = t + i * 256;
                cp16(((char*)S.Bs[nb]) + u * 16, Bf + (size_t)(sc + 1) * 8192 + (size_t)u * 8);
            }
            CP_COMMIT();
        }
        {
            int r = t >> 1, kb = (t & 1) * 8;
            int i = r & 15, rb = r & ~15;
            float d = S.sd[i];
            const float* xrow = &S.Xs[buf][r][kb];
#pragma unroll
            for (int q = 0; q < 8; q++) {
                float u = d * xrow[q];
                __half uh = __float2half_rn(u);
                S.Ah[0][r][kb + q] = uh;
                S.Al[0][r][kb + q] = __float2half_rn(u - __half2float(uh));
            }
            unsigned long long vacc[4];
#pragma unroll
            for (int q = 0; q < 4; q++) vacc[q] = pack2(0.f, 0.f);
#pragma unroll
            for (int j = 0; j < 16; j++) {
                float aij = S.sA[i][j];
                unsigned long long ap = pack2(aij, aij);
                const unsigned long long* xr = (const unsigned long long*)&S.Xs[buf][rb + j][kb];
#pragma unroll
                for (int q = 0; q < 4; q++) vacc[q] = ffma2(ap, xr[q], vacc[q]);
            }
#pragma unroll
            for (int q = 0; q < 4; q++) {
                float v0, v1; unpack2(vacc[q], v0, v1);
                __half h0 = __float2half_rn(v0), h1 = __float2half_rn(v1);
                S.Ah[1][r][kb + q * 2] = h0;
                S.Ah[1][r][kb + q * 2 + 1] = h1;
                S.Al[1][r][kb + q * 2] = __float2half_rn(v0 - __half2float(h0));
                S.Al[1][r][kb + q * 2 + 1] = __float2half_rn(v1 - __half2float(h1));
            }
        }
        __syncthreads();
#pragma unroll
        for (int pr = 0; pr < 2; pr++) {
            uint32_t ah[2][4], al[2][4];
            int lr = lane & 7, sel = lane >> 3;
            int rofs = (sel & 1) * 8 + lr, cofs = (sel >> 1) * 8;
#pragma unroll
            for (int mf = 0; mf < 2; mf++) {
                int row = wm * 32 + mf * 16 + rofs;
                uint32_t ao = (uint32_t)((pr * 128 + row) * A_STR + cofs) * 2;
                ldm4(ah[mf], smbase + AhOff + ao);
                ldm4(al[mf], smbase + AlOff + ao);
            }
#pragma unroll
            for (int nf = 0; nf < 8; nf++) {
                uint32_t bb = smbase + BsOff + (uint32_t)buf * 16384 +
                              (uint32_t)pr * 8192 + (uint32_t)(wn * 8 + nf) * 256 +
                              (uint32_t)lane * 8;
                uint32_t bh0, bh1, bl0, bl1;
                lds64(bh0, bh1, bb);
                lds64(bl0, bl1, bb + 4096);
#pragma unroll
                for (int mf = 0; mf < 2; mf++) {
                    mma16816(acc[mf][nf], ah[mf], bh0, bh1);
                    mma16816(acc[mf][nf], al[mf], bh0, bh1);
                    mma16816(acc[mf][nf], ah[mf], bl0, bl1);
                }
            }
        }
    }
#pragma unroll
    for (int mf = 0; mf < 2; mf++) {
        int r0 = m0 + wm * 32 + mf * 16 + (lane >> 2);
#pragma unroll
        for (int nf = 0; nf < 8; nf++) {
            int cg = wn * 64 + nf * 8 + (lane & 3) * 2;
            float s0 = S.scl[cg], s1 = S.scl[cg + 1];
            float h0 = S.shf[cg], h1 = S.shf[cg + 1];
            float y0 = fmaxf(acc[mf][nf][0] * s0 + h0, 0.f);
            float y1 = fmaxf(acc[mf][nf][1] * s1 + h1, 0.f);
            float y2 = fmaxf(acc[mf][nf][2] * s0 + h0, 0.f);
            float y3 = fmaxf(acc[mf][nf][3] * s1 + h1, 0.f);
            if (R) {
                y0 += R[r0 * HID + cg];       y1 += R[r0 * HID + cg + 1];
                y2 += R[(r0 + 8) * HID + cg]; y3 += R[(r0 + 8) * HID + cg + 1];
            }
            float2 v0; v0.x = y0; v0.y = y1;
            float2 v1; v1.x = y2; v1.y = y3;
            *(float2*)&Y[r0 * HID + cg] = v0;
            *(float2*)&Y[(r0 + 8) * HID + cg] = v1;
        }
    }
}

// ---------------- output layer + MDN: postmix, 64 rows/block ----------------
struct OutSm {
    float hs[64][132];
    float Ws[256][26];
    float P1[64][26];
    float sA[16][16];
    float sdv[16];
    float bo[25];
};

__global__ void __launch_bounds__(256) out_kernel(const float* __restrict__ Wout,
                                                  const float* __restrict__ bout,
                                                  float* __restrict__ out) {
    extern __shared__ __align__(16) char osmraw[];
    OutSm& S = *reinterpret_cast<OutSm*>(osmraw);
    const int t = threadIdx.x;
    const int m0 = blockIdx.x * 64;
    S.sA[t >> 4][t & 15] = g_Aoff[9][t >> 4][t & 15];
    if (t < 16) S.sdv[t] = g_d[9][t];
    if (t < 25) S.bo[t] = bout[t];
    for (int idx = t; idx < 2048; idx += 256) {
        int r = idx >> 5, q = idx & 31;
        *(float4*)&S.hs[r][q * 4] = *(const float4*)&g_h[(size_t)(m0 + r) * HID + q * 4];
    }
    for (int idx = t; idx < 6400; idx += 256) {
        int s = idx / 3200, rr = idx - s * 3200;
        int k = rr / 25, c = rr - k * 25;
        S.Ws[s * 128 + k][c] = Wout[idx];
    }
    __syncthreads();
    const int r = t >> 2, cs = t & 3;
    const int i = r & 15, rb = r & ~15;
    int cols[7]; int nc = 0;
    for (int c = cs; c < 25; c += 4) { cols[nc] = c; nc++; }
    float p0[7], p1[7];
#pragma unroll
    for (int q = 0; q < 7; q++) { p0[q] = 0.f; p1[q] = 0.f; }
    for (int k = 0; k < HID; k++) {
        float h = S.hs[r][k];
#pragma unroll
        for (int q = 0; q < 7; q++)
            if (q < nc) {
                p0[q] += h * S.Ws[k][cols[q]];
                p1[q] += h * S.Ws[128 + k][cols[q]];
            }
    }
    for (int q = 0; q < nc; q++) S.P1[r][cols[q]] = p1[q];
    __syncthreads();
    float d = S.sdv[i];
    for (int q = 0; q < nc; q++) {
        int c = cols[q];
        float o = d * p0[q] + S.bo[c];
#pragma unroll
        for (int j = 0; j < 16; j++) o += S.sA[i][j] * S.P1[rb + j][c];
        int row = m0 + r;
        if (c < 15) {
            out[(size_t)row * 15 + c] = tanhf(o);
        } else if (c < 20) {
            float sg = (o > 0.f) ? (o + 1.f) : expf(o);
            out[(size_t)MROWS * 15 + (size_t)row * 5 + (c - 15)] = fmaxf(sg, 1e-10f);
        } else {
            out[(size_t)MROWS * 20 + (size_t)row * 5 + (c - 20)] = o;
        }
    }
}

extern "C" void kernel_launch(void* const* d_in, const int* in_sizes, int n_in,
                              void* d_out, int out_size) {
    const float* x      = (const float*)d_in[0];
    const float* W_in   = (const float*)d_in[1];
    const float* e_in   = (const float*)d_in[2];
    const float* b_in   = (const float*)d_in[3];
    const float* bn_in  = (const float*)d_in[4];
    const float* W_mid  = (const float*)d_in[5];
    const float* e_mid  = (const float*)d_in[6];
    const float* b_mid  = (const float*)d_in[7];
    const float* bn_mid = (const float*)d_in[8];
    const float* W_out  = (const float*)d_in[9];
    const float* e_out  = (const float*)d_in[10];
    const float* b_out  = (const float*)d_in[11];
    float* out = (float*)d_out;

    static int smem_set = 0;
    if (!smem_set) {
        cudaFuncSetAttribute(mid_mma, cudaFuncAttributeMaxDynamicSharedMemorySize,
                             (int)sizeof(MidSm));
        cudaFuncSetAttribute(out_kernel, cudaFuncAttributeMaxDynamicSharedMemorySize,
                             (int)sizeof(OutSm));
        smem_set = 1;
    }

    prep_kernel<<<1, 256>>>(e_in, bn_in, b_in, e_mid, bn_mid, b_mid, e_out);
    wprep_kernel<<<2048, 256>>>(W_mid);
    in_kernel<<<2048, 256>>>(x, W_in);

    const int nblk = MROWS / 128;
    const size_t smb = sizeof(MidSm);
    __half* bfh = nullptr;
    cudaGetSymbolAddress((void**)&bfh, g_Bfrag);
    float *gh = nullptr, *gt = nullptr;
    cudaGetSymbolAddress((void**)&gh, g_h);
    cudaGetSymbolAddress((void**)&gt, g_t);
    for (int p = 0; p < 4; p++) {
        mid_mma<<<nblk, 256, smb>>>(gh, gt, nullptr, bfh + (size_t)(2 * p) * 65536, 1 + 2 * p);
        mid_mma<<<nblk, 256, smb>>>(gt, gh, gh, bfh + (size_t)(2 * p + 1) * 65536, 2 + 2 * p);
    }
    out_kernel<<<MROWS / 64, 256, sizeof(OutSm)>>>(W_out, b_out, out);
}